// round 9
// baseline (speedup 1.0000x reference)
#include <cuda_runtime.h>
#include <cuda_fp16.h>
#include <math.h>

#define NN   99000
#define NH   64
#define NNZC 1584000
#define NADJ 6
#define NPT  33000
#define NT   97               // scan tiles per adjacency: ceil(99000/1024)
#define PACKC (NNZC + NN)     // per-adjacency pack capacity (padding slack)

// ---------------- scratch (device globals; no runtime allocation) ----------------
__device__ __half g_st[2][3][NN * NH];   // fp16 states s0,s1,s2 per meta
__device__ float  g_t[2][NN * NH];       // gelu output per meta
__device__ float  g_logits[NN * 2];
__device__ float  g_Wc[2][3][NH * NH];   // composed weights, transposed: [k_in*64 + i_out]
__device__ float  g_bc[2][3][NH];        // composed biases

// CSR scratch
__device__ int  g_cursor[NADJ * NN];
__device__ int  g_rowptr[NADJ * (NN + 1)];
__device__ int  g_tilesum[NADJ * NT];
__device__ int  g_tileoff[NADJ * NT];
__device__ __align__(16) int2 g_pack[(size_t)NADJ * PACKC];  // (col, val bits), even-padded rows

__device__ __forceinline__ const __half* st_ptr(int m, int id) {
    return g_st[m][id];
}

__device__ __forceinline__ float warp_sum(float v) {
    #pragma unroll
    for (int o = 16; o > 0; o >>= 1) v += __shfl_xor_sync(0xffffffffu, v, o);
    return v;
}

// ---------------- CSR build ----------------
__global__ void zero_counts_kernel() {
    int i = blockIdx.x * 256 + threadIdx.x;
    if (i < NADJ * NN) g_cursor[i] = 0;
}

__global__ void hist_kernel(const int* __restrict__ rows) {
    int i = blockIdx.x * 256 + threadIdx.x;
    if (i >= NADJ * NNZC / 8) return;
    int a = (i * 8) / NNZC;
    int4 r0 = *(const int4*)&rows[i * 8];
    int4 r1 = *(const int4*)&rows[i * 8 + 4];
    int* cnt = g_cursor + a * NN;
    atomicAdd(&cnt[r0.x], 1); atomicAdd(&cnt[r0.y], 1);
    atomicAdd(&cnt[r0.z], 1); atomicAdd(&cnt[r0.w], 1);
    atomicAdd(&cnt[r1.x], 1); atomicAdd(&cnt[r1.y], 1);
    atomicAdd(&cnt[r1.z], 1); atomicAdd(&cnt[r1.w], 1);
}

// phase A: per-tile local exclusive scan over EVEN-PADDED counts
__global__ void scanA_kernel() {
    __shared__ int sh[32];
    int a = blockIdx.y, tile = blockIdx.x;
    int idx = tile * 1024 + threadIdx.x;
    int lane = threadIdx.x & 31, wid = threadIdx.x >> 5;
    int v = (idx < NN) ? g_cursor[a * NN + idx] : 0;
    int vp = v + (v & 1);                 // pad odd rows to even length
    int s = vp;
    #pragma unroll
    for (int o = 1; o < 32; o <<= 1) {
        int n = __shfl_up_sync(0xffffffffu, s, o);
        if (lane >= o) s += n;
    }
    if (lane == 31) sh[wid] = s;
    __syncthreads();
    if (wid == 0) {
        int w = sh[lane];
        #pragma unroll
        for (int o = 1; o < 32; o <<= 1) {
            int n = __shfl_up_sync(0xffffffffu, w, o);
            if (lane >= o) w += n;
        }
        sh[lane] = w;
    }
    __syncthreads();
    int incl = s + ((wid > 0) ? sh[wid - 1] : 0);
    if (idx < NN) g_rowptr[a * (NN + 1) + idx] = incl - vp;
    if (threadIdx.x == 1023) g_tilesum[a * NT + tile] = incl;
}

__global__ void scanB_kernel() {
    __shared__ int sh[4];
    int a = blockIdx.x, t = threadIdx.x;
    int lane = t & 31, wid = t >> 5;
    int orig = (t < NT) ? g_tilesum[a * NT + t] : 0;
    int s = orig;
    #pragma unroll
    for (int o = 1; o < 32; o <<= 1) {
        int n = __shfl_up_sync(0xffffffffu, s, o);
        if (lane >= o) s += n;
    }
    if (lane == 31) sh[wid] = s;
    __syncthreads();
    int add = 0;
    for (int w = 0; w < wid; w++) add += sh[w];
    int incl = s + add;
    if (t < NT) g_tileoff[a * NT + t] = incl - orig;
    if (t == NT - 1) g_rowptr[a * (NN + 1) + NN] = incl;
}

// phase C: finalize rowptr & cursor; zero the pad slot of odd rows
__global__ void scanC_kernel() {
    int a = blockIdx.y;
    int idx = blockIdx.x * 1024 + threadIdx.x;
    if (idx >= NN) return;
    int cnt = g_cursor[a * NN + idx];     // original count (pre-overwrite)
    int off = g_tileoff[a * NT + blockIdx.x];
    int e = g_rowptr[a * (NN + 1) + idx] + off;
    g_rowptr[a * (NN + 1) + idx] = e;
    g_cursor[a * NN + idx] = e;
    if (cnt & 1) g_pack[(size_t)a * PACKC + e + cnt] = make_int2(0, 0);  // zero sentinel
}

__global__ void scatter_kernel(const int* __restrict__ rows, const int* __restrict__ cols,
                               const float* __restrict__ vals) {
    int i = blockIdx.x * 256 + threadIdx.x;
    if (i >= NADJ * NNZC / 8) return;
    int a = (i * 8) / NNZC;
    int* cur = g_cursor + a * NN;
    int2* pk = (int2*)(g_pack + (size_t)a * PACKC);
    #pragma unroll
    for (int h = 0; h < 2; h++) {
        int base = i * 8 + h * 4;
        int4 r = *(const int4*)&rows[base];
        int4 c = *(const int4*)&cols[base];
        float4 v = *(const float4*)&vals[base];
        int p0 = atomicAdd(&cur[r.x], 1);
        int p1 = atomicAdd(&cur[r.y], 1);
        int p2 = atomicAdd(&cur[r.z], 1);
        int p3 = atomicAdd(&cur[r.w], 1);
        pk[p0] = make_int2(c.x, __float_as_int(v.x));
        pk[p1] = make_int2(c.y, __float_as_int(v.y));
        pk[p2] = make_int2(c.z, __float_as_int(v.z));
        pk[p3] = make_int2(c.w, __float_as_int(v.w));
    }
}

// ---------------- weight composition ----------------
__global__ void wcomb_kernel(const float* __restrict__ cW, const float* __restrict__ cb,
                             const float* __restrict__ wsW, const float* __restrict__ wsb) {
    __shared__ float cs[64][65];
    __shared__ float ws[64][65];
    int blk = blockIdx.x;
    int m = blk / 3;
    int t = blk % 3;
    int tid = threadIdx.x;
    for (int i = tid; i < 4096; i += 256) {
        int r = i >> 6, c = i & 63;
        cs[r][c] = cW[m * 4096 + i];
        ws[r][c] = wsW[t * 4096 + i];
    }
    __syncthreads();
    for (int e = tid; e < 4096; e += 256) {
        int i = e >> 6, k = e & 63;
        float acc = 0.f;
        #pragma unroll
        for (int q = 0; q < 64; q++) acc += cs[i][q] * ws[q][k];
        g_Wc[m][t][k * 64 + i] = acc;
    }
    if (tid < 64) {
        float acc = cb[m * 64 + tid];
        #pragma unroll
        for (int q = 0; q < 64; q++) acc += cs[tid][q] * wsb[t * 64 + q];
        g_bc[m][t][tid] = acc;
    }
}

// ---------------- fused s0: both metas from feats directly ----------------
__global__ void s0_kernel(const float* __restrict__ f0, const float* __restrict__ f1,
                          const float* __restrict__ f2) {
    __shared__ float Xs[64][68];
    __shared__ float Wt[64][64];
    __shared__ float bs[64];
    int type = blockIdx.y;
    const float* X = (type == 0) ? f0 : (type == 1) ? f1 : f2;
    int t = threadIdx.x;
    int lrow0 = blockIdx.x * 64;
    for (int i = t; i < 1024; i += 256) {
        int r = i >> 4, q = i & 15;
        float4 v = make_float4(0.f, 0.f, 0.f, 0.f);
        if (lrow0 + r < NPT) v = *(const float4*)&X[(size_t)(lrow0 + r) * 64 + q * 4];
        *(float4*)&Xs[r][q * 4] = v;
    }
    int nd = t >> 3;
    int cg = (t & 7) * 8;
    #pragma unroll
    for (int m = 0; m < 2; m++) {
        __syncthreads();
        for (int i = t; i < 4096; i += 256) ((float*)Wt)[i] = g_Wc[m][type][i];
        if (t < 64) bs[t] = g_bc[m][type][t];
        __syncthreads();
        float acc0[8], acc1[8];
        #pragma unroll
        for (int j = 0; j < 8; j++) { acc0[j] = bs[cg + j]; acc1[j] = bs[cg + j]; }
        #pragma unroll
        for (int k = 0; k < 64; k++) {
            float x0 = Xs[nd][k];
            float x1 = Xs[nd + 32][k];
            float4 w0 = *(const float4*)&Wt[k][cg];
            float4 w1 = *(const float4*)&Wt[k][cg + 4];
            acc0[0] += x0 * w0.x; acc0[1] += x0 * w0.y; acc0[2] += x0 * w0.z; acc0[3] += x0 * w0.w;
            acc0[4] += x0 * w1.x; acc0[5] += x0 * w1.y; acc0[6] += x0 * w1.z; acc0[7] += x0 * w1.w;
            acc1[0] += x1 * w0.x; acc1[1] += x1 * w0.y; acc1[2] += x1 * w0.z; acc1[3] += x1 * w0.w;
            acc1[4] += x1 * w1.x; acc1[5] += x1 * w1.y; acc1[6] += x1 * w1.z; acc1[7] += x1 * w1.w;
        }
        __half* D = (__half*)g_st[m][0];
        int r0 = type * NPT + lrow0 + nd;
        int r1 = r0 + 32;
        if (lrow0 + nd < NPT) {
            __half2* yp = (__half2*)&D[(size_t)r0 * 64 + cg];
            yp[0] = __floats2half2_rn(acc0[0], acc0[1]);
            yp[1] = __floats2half2_rn(acc0[2], acc0[3]);
            yp[2] = __floats2half2_rn(acc0[4], acc0[5]);
            yp[3] = __floats2half2_rn(acc0[6], acc0[7]);
        }
        if (lrow0 + nd + 32 < NPT) {
            __half2* yp = (__half2*)&D[(size_t)r1 * 64 + cg];
            yp[0] = __floats2half2_rn(acc1[0], acc1[1]);
            yp[1] = __floats2half2_rn(acc1[2], acc1[3]);
            yp[2] = __floats2half2_rn(acc1[4], acc1[5]);
            yp[3] = __floats2half2_rn(acc1[6], acc1[7]);
        }
    }
}

// ---------------- gather core: one CSR pass over an even-padded row ----------------
// m4 covers 2 edges: {col0, valbits0, col1, valbits1}
#define GATH2(m4)                                                                  \
    {                                                                              \
        float2 xa = __half22float2(*(const __half2*)&S[(size_t)(m4).x * 64 + lane2]); \
        float2 xb = __half22float2(*(const __half2*)&S[(size_t)(m4).z * 64 + lane2]); \
        float va = __int_as_float((m4).y), vb = __int_as_float((m4).w);            \
        ax += va * xa.x; ay += va * xa.y;                                          \
        ax += vb * xb.x; ay += vb * xb.y;                                          \
    }

__device__ __forceinline__ void gath_pass(const __half* __restrict__ S, int aidx,
                                          int row, int lane2, float& ax, float& ay) {
    const int* rp = g_rowptr + aidx * (NN + 1);
    int j   = rp[row];
    int end = rp[row + 1];
    const int2* __restrict__ pk = g_pack + (size_t)aidx * PACKC;
    for (; j + 16 <= end; j += 16) {
        const int4* q = (const int4*)(pk + j);   // 16B-aligned: j even, base aligned
        int4 m0 = q[0], m1 = q[1], m2 = q[2], m3 = q[3];
        int4 m4 = q[4], m5 = q[5], m6 = q[6], m7 = q[7];
        GATH2(m0) GATH2(m1) GATH2(m2) GATH2(m3)
        GATH2(m4) GATH2(m5) GATH2(m6) GATH2(m7)
    }
    for (; j + 4 <= end; j += 4) {
        const int4* q = (const int4*)(pk + j);
        int4 m0 = q[0], m1 = q[1];
        GATH2(m0) GATH2(m1)
    }
    if (j < end) {           // exactly 2 edges remain (rows are even-length)
        int4 m0 = *(const int4*)(pk + j);
        GATH2(m0)
    }
}

// ---------------- gather SpMM steps 1 & 2 (fp16 out), grid.y = meta ----------------
template<int NP>
__global__ void spmm_gather_kernel(const int* __restrict__ idxes_seq,
                                   const int* __restrict__ idxes_res) {
    int m = blockIdx.y;
    int gid = blockIdx.x * 256 + threadIdx.x;
    int row = gid >> 5;
    if (row >= NN) return;
    int lane2 = (threadIdx.x & 31) * 2;
    const int* seq = idxes_seq + m * 3;
    const int* res = idxes_res + m * 3;

    float ax = 0.f, ay = 0.f;
    if (NP == 1) {
        gath_pass(st_ptr(m, 0), seq[0], row, lane2, ax, ay);
    } else {
        gath_pass(st_ptr(m, 1), seq[1], row, lane2, ax, ay);
        gath_pass(st_ptr(m, 0), res[0], row, lane2, ax, ay);
    }
    __half* D = (__half*)st_ptr(m, NP);
    *(__half2*)&D[(size_t)row * 64 + lane2] = __floats2half2_rn(ax, ay);
}

// ---------------- final gather + layernorm + gelu + attention logit, grid.y = meta ----------------
__global__ void spmm_final_kernel(const int* __restrict__ idxes_seq,
                                  const int* __restrict__ idxes_res,
                                  const float* __restrict__ norm_g,
                                  const float* __restrict__ norm_b,
                                  const float* __restrict__ A1, const float* __restrict__ b1,
                                  const float* __restrict__ a2, const float* __restrict__ b2) {
    __shared__ float A1s[64][68];
    __shared__ float hs[8][68];
    __shared__ float b1s[64];
    __shared__ float a2s[64];
    int m = blockIdx.y;
    int t = threadIdx.x;
    for (int i = t; i < 4096; i += 256) {
        int a = i >> 6, k = i & 63;
        A1s[a][k] = A1[i];
    }
    if (t < 64) { b1s[t] = b1[t]; a2s[t] = a2[t]; }
    __syncthreads();

    int w = t >> 5;
    int lane = t & 31;
    int lane2 = lane * 2;
    int row = blockIdx.x * 8 + w;
    if (row >= NN) return;
    const int* seq = idxes_seq + m * 3;
    const int* res = idxes_res + m * 3;

    float ax = 0.f, ay = 0.f;
    gath_pass(st_ptr(m, 2), seq[2], row, lane2, ax, ay);
    gath_pass(st_ptr(m, 0), res[1], row, lane2, ax, ay);
    gath_pass(st_ptr(m, 1), res[2], row, lane2, ax, ay);

    // layernorm (row distributed 2 cols/lane) + gelu
    float mu = warp_sum(ax + ay) * (1.0f / 64.0f);
    float d0 = ax - mu, d1 = ay - mu;
    float var = warp_sum(d0 * d0 + d1 * d1) * (1.0f / 64.0f);
    float rstd = rsqrtf(var + 1e-5f);
    float2 gv = *(const float2*)&norm_g[m * 64 + lane2];
    float2 bv = *(const float2*)&norm_b[m * 64 + lane2];
    float n0 = d0 * rstd * gv.x + bv.x;
    float n1 = d1 * rstd * gv.y + bv.y;
    float ge0 = 0.5f * n0 * (1.0f + erff(n0 * 0.70710678118654752f));
    float ge1 = 0.5f * n1 * (1.0f + erff(n1 * 0.70710678118654752f));
    *(float2*)&g_t[m][(size_t)row * 64 + lane2] = make_float2(ge0, ge1);
    hs[w][lane2] = ge0;
    hs[w][lane2 + 1] = ge1;
    __syncwarp();

    // logit = tanh(A1 h + b1) . a2 + b2
    float part = 0.f;
    #pragma unroll
    for (int half = 0; half < 2; half++) {
        int a = lane + half * 32;
        float acc = b1s[a];
        #pragma unroll
        for (int k4 = 0; k4 < 16; k4++) {
            float4 wv = *(const float4*)&A1s[a][k4 * 4];
            float4 hv = *(const float4*)&hs[w][k4 * 4];
            acc += wv.x * hv.x + wv.y * hv.y + wv.z * hv.z + wv.w * hv.w;
        }
        part += tanhf(acc) * a2s[a];
    }
    part = warp_sum(part);
    if (lane == 0) g_logits[row * 2 + m] = part + b2[0];
}

// ---------------- 2-way softmax over metas + weighted sum -> out ----------------
__global__ void mix_kernel(float* __restrict__ out) {
    int idx = blockIdx.x * 256 + threadIdx.x;
    if (idx >= NN * 16) return;
    int node = idx >> 4, q = idx & 15;
    float l0 = g_logits[node * 2 + 0];
    float l1 = g_logits[node * 2 + 1];
    float mx = fmaxf(l0, l1);
    float e0 = expf(l0 - mx), e1 = expf(l1 - mx);
    float inv = 1.0f / (e0 + e1);
    float w0 = e0 * inv, w1 = e1 * inv;
    float4 a = *(const float4*)&g_t[0][(size_t)node * 64 + q * 4];
    float4 b = *(const float4*)&g_t[1][(size_t)node * 64 + q * 4];
    *(float4*)&out[(size_t)node * 64 + q * 4] =
        make_float4(w0 * a.x + w1 * b.x, w0 * a.y + w1 * b.y,
                    w0 * a.z + w1 * b.z, w0 * a.w + w1 * b.w);
}

extern "C" void kernel_launch(void* const* d_in, const int* in_sizes, int n_in,
                              void* d_out, int out_size) {
    const float* feats0      = (const float*)d_in[0];
    const float* feats1      = (const float*)d_in[1];
    const float* feats2      = (const float*)d_in[2];
    const float* ws_W        = (const float*)d_in[3];
    const float* ws_b        = (const float*)d_in[4];
    const float* adj_vals    = (const float*)d_in[5];
    const float* cell_aff_W  = (const float*)d_in[6];
    const float* cell_aff_b  = (const float*)d_in[7];
    const float* cell_norm_g = (const float*)d_in[8];
    const float* cell_norm_b = (const float*)d_in[9];
    const float* attn1_W     = (const float*)d_in[10];
    const float* attn1_b     = (const float*)d_in[11];
    const float* attn2_W     = (const float*)d_in[12];
    const float* attn2_b     = (const float*)d_in[13];
    // d_in[14] = node_types (contiguous blocks; unused)
    const int* adj_rows      = (const int*)d_in[15];
    const int* adj_cols      = (const int*)d_in[16];
    const int* idxes_seq     = (const int*)d_in[17];   // [2,3]
    const int* idxes_res     = (const int*)d_in[18];   // [2,3]
    float* out = (float*)d_out;

    const int S0_BLOCKS    = (NPT + 63) / 64;
    const int EDGE8_BLOCKS = (NADJ * NNZC / 8 + 255) / 256;
    const int CNT_BLOCKS   = (NADJ * NN + 255) / 256;
    const int GATH_BLOCKS  = (NN * 32 + 255) / 256;
    const int FIN_BLOCKS   = (NN + 7) / 8;
    const int MIX_BLOCKS   = (NN * 16 + 255) / 256;

    // ---- CSR build (even-padded rows) ----
    zero_counts_kernel<<<CNT_BLOCKS, 256>>>();
    hist_kernel<<<EDGE8_BLOCKS, 256>>>(adj_rows);
    scanA_kernel<<<dim3(NT, NADJ), 1024>>>();
    scanB_kernel<<<NADJ, 128>>>();
    scanC_kernel<<<dim3(NT, NADJ), 1024>>>();
    scatter_kernel<<<EDGE8_BLOCKS, 256>>>(adj_rows, adj_cols, adj_vals);

    // ---- composed weights + fused s0 (both metas) ----
    wcomb_kernel<<<6, 256>>>(cell_aff_W, cell_aff_b, ws_W, ws_b);
    s0_kernel<<<dim3(S0_BLOCKS, 3), 256>>>(feats0, feats1, feats2);

    // ---- state chain, both metas per launch ----
    spmm_gather_kernel<1><<<dim3(GATH_BLOCKS, 2), 256>>>(idxes_seq, idxes_res);
    spmm_gather_kernel<2><<<dim3(GATH_BLOCKS, 2), 256>>>(idxes_seq, idxes_res);
    spmm_final_kernel<<<dim3(FIN_BLOCKS, 2), 256>>>(idxes_seq, idxes_res,
                                                    cell_norm_g, cell_norm_b,
                                                    attn1_W, attn1_b, attn2_W, attn2_b);

    mix_kernel<<<MIX_BLOCKS, 256>>>(out);
}